// round 1
// baseline (speedup 1.0000x reference)
#include <cuda_runtime.h>

#define N_NODES   100000
#define N_EDGES   1200000
#define D         64
#define G_FEAT    128
#define N_GRAPHS  256

// Scratch (no allocations allowed -> __device__ globals)
__device__ float g_agg[N_NODES * D];   // 25.6 MB
__device__ float g_Weff[D];
__device__ float g_c;

// ---------------------------------------------------------------------------
// Zero the aggregation buffer (float4 stores)
// ---------------------------------------------------------------------------
__global__ void k_zero_agg() {
    int i = blockIdx.x * blockDim.x + threadIdx.x;
    if (i < (N_NODES * D) / 4) {
        ((float4*)g_agg)[i] = make_float4(0.f, 0.f, 0.f, 0.f);
    }
}

// ---------------------------------------------------------------------------
// Precompute W_eff = W_out @ W_pred, c = b_out . W_pred, init out = b_pred
// ---------------------------------------------------------------------------
__global__ void k_prep(const float* __restrict__ W_out,
                       const float* __restrict__ b_out,
                       const float* __restrict__ W_pred,
                       const float* __restrict__ b_pred,
                       float* __restrict__ out) {
    int t = threadIdx.x;
    if (t < D) {
        float s = 0.f;
        #pragma unroll 4
        for (int f = 0; f < G_FEAT; f++) s += W_out[t * G_FEAT + f] * W_pred[f];
        g_Weff[t] = s;
    }
    if (t == 0) {
        float s = 0.f;
        for (int f = 0; f < G_FEAT; f++) s += b_out[f] * W_pred[f];
        g_c = s;
    }
    if (t < N_GRAPHS) out[t] = b_pred[0];
}

// ---------------------------------------------------------------------------
// Edge scatter: agg[dst] += node_feats[src].  16 threads per edge, float4 each.
// ---------------------------------------------------------------------------
__global__ void __launch_bounds__(256) k_edges(const float* __restrict__ nf,
                                               const int* __restrict__ src,
                                               const int* __restrict__ dst) {
    long long t = (long long)blockIdx.x * blockDim.x + threadIdx.x;
    int e = (int)(t >> 4);
    int j = (int)(t & 15);
    if (e >= N_EDGES) return;
    int s = src[e];
    int d = dst[e];
    float4 v = ((const float4*)(nf + (size_t)s * D))[j];
    float* p = g_agg + (size_t)d * D + j * 4;
    atomicAdd(p + 0, v.x);
    atomicAdd(p + 1, v.y);
    atomicAdd(p + 2, v.z);
    atomicAdd(p + 3, v.w);
}

// ---------------------------------------------------------------------------
// Fused node pipeline:
//   h  = relu(agg@W1+b1) + relu(x@W2+b2)
//   h2 = relu(h@W3+b3)
//   s  = h2 . W_eff ;  out[gid[n]] += s + c
// CTA: 256 threads, 64 nodes.  Register tile 4 nodes x 4 outputs per thread.
// ---------------------------------------------------------------------------
#define TPAD 68                       // padded tile row stride (floats)
#define SMEM_FLOATS (3*4096 + 2*64*TPAD + 4*64)
#define SMEM_BYTES  (SMEM_FLOATS * 4)

__global__ void __launch_bounds__(256) k_nodes(
    const float* __restrict__ nf, const int* __restrict__ gid,
    const float* __restrict__ W1, const float* __restrict__ b1,
    const float* __restrict__ W2, const float* __restrict__ b2,
    const float* __restrict__ W3, const float* __restrict__ b3,
    float* __restrict__ out) {

    extern __shared__ __align__(16) float sm[];
    float* sW1 = sm;                  // [64][64] k-major
    float* sW2 = sW1 + 4096;
    float* sW3 = sW2 + 4096;
    float* sA  = sW3 + 4096;          // [64][TPAD]  aggT, later hT
    float* sX  = sA + 64 * TPAD;      // [64][TPAD]  xT
    float* sb1 = sX + 64 * TPAD;
    float* sb2 = sb1 + 64;
    float* sb3 = sb2 + 64;
    float* swe = sb3 + 64;
    __shared__ float snode[64];

    int tid = threadIdx.x;
    int node0 = blockIdx.x * 64;

    // --- load weights (straight copy, float4) ---
    #pragma unroll
    for (int i = 0; i < 4; i++) {
        int idx = tid + i * 256;      // 1024 float4 slots per matrix
        ((float4*)sW1)[idx] = ((const float4*)W1)[idx];
        ((float4*)sW2)[idx] = ((const float4*)W2)[idx];
        ((float4*)sW3)[idx] = ((const float4*)W3)[idx];
    }
    if (tid < 64) {
        sb1[tid] = b1[tid];
        sb2[tid] = b2[tid];
        sb3[tid] = b3[tid];
        swe[tid] = g_Weff[tid];
        snode[tid] = 0.f;
    }

    // --- stage node tiles transposed: sT[k][n] ---
    {
        int r = tid >> 2;             // node row within tile, 0..63
        int q = tid & 3;              // quarter of the 64-float row
        int node = node0 + r;
        bool ok = node < N_NODES;
        #pragma unroll
        for (int u = 0; u < 4; u++) {
            int k0 = q * 16 + u * 4;
            float4 a = make_float4(0.f, 0.f, 0.f, 0.f);
            float4 x = make_float4(0.f, 0.f, 0.f, 0.f);
            if (ok) {
                a = ((const float4*)(g_agg + (size_t)node * D))[k0 >> 2];
                x = ((const float4*)(nf    + (size_t)node * D))[k0 >> 2];
            }
            sA[(k0 + 0) * TPAD + r] = a.x;
            sA[(k0 + 1) * TPAD + r] = a.y;
            sA[(k0 + 2) * TPAD + r] = a.z;
            sA[(k0 + 3) * TPAD + r] = a.w;
            sX[(k0 + 0) * TPAD + r] = x.x;
            sX[(k0 + 1) * TPAD + r] = x.y;
            sX[(k0 + 2) * TPAD + r] = x.z;
            sX[(k0 + 3) * TPAD + r] = x.w;
        }
    }
    __syncthreads();

    int tx = tid & 15;                // node group:  nodes 4*tx + i
    int ty = tid >> 4;                // out  group:  feats 4*ty + m

    float accA[4][4], accB[4][4];
    #pragma unroll
    for (int i = 0; i < 4; i++)
        #pragma unroll
        for (int m = 0; m < 4; m++) { accA[i][m] = 0.f; accB[i][m] = 0.f; }

    // --- stage 1: two GEMMs (agg@W1, x@W2) ---
    #pragma unroll 8
    for (int k = 0; k < 64; k++) {
        float4 av = *(const float4*)(sA + k * TPAD + 4 * tx);
        float4 xv = *(const float4*)(sX + k * TPAD + 4 * tx);
        float4 w1 = *(const float4*)(sW1 + k * 64 + 4 * ty);
        float4 w2 = *(const float4*)(sW2 + k * 64 + 4 * ty);
        float a[4] = {av.x, av.y, av.z, av.w};
        float x[4] = {xv.x, xv.y, xv.z, xv.w};
        float p[4] = {w1.x, w1.y, w1.z, w1.w};
        float q[4] = {w2.x, w2.y, w2.z, w2.w};
        #pragma unroll
        for (int i = 0; i < 4; i++)
            #pragma unroll
            for (int m = 0; m < 4; m++) {
                accA[i][m] += a[i] * p[m];
                accB[i][m] += x[i] * q[m];
            }
    }

    float h[4][4];
    #pragma unroll
    for (int i = 0; i < 4; i++)
        #pragma unroll
        for (int m = 0; m < 4; m++) {
            int j = 4 * ty + m;
            h[i][m] = fmaxf(accA[i][m] + sb1[j], 0.f) +
                      fmaxf(accB[i][m] + sb2[j], 0.f);
        }

    __syncthreads();                  // everyone done reading sA
    // store hT into sA: sA[j][n]
    #pragma unroll
    for (int m = 0; m < 4; m++) {
        float4 v = make_float4(h[0][m], h[1][m], h[2][m], h[3][m]);
        *(float4*)(sA + (4 * ty + m) * TPAD + 4 * tx) = v;
    }
    __syncthreads();

    // --- stage 2: h @ W3 ---
    float accC[4][4];
    #pragma unroll
    for (int i = 0; i < 4; i++)
        #pragma unroll
        for (int m = 0; m < 4; m++) accC[i][m] = 0.f;

    #pragma unroll 8
    for (int k = 0; k < 64; k++) {
        float4 av = *(const float4*)(sA + k * TPAD + 4 * tx);
        float4 w3 = *(const float4*)(sW3 + k * 64 + 4 * ty);
        float a[4] = {av.x, av.y, av.z, av.w};
        float p[4] = {w3.x, w3.y, w3.z, w3.w};
        #pragma unroll
        for (int i = 0; i < 4; i++)
            #pragma unroll
            for (int m = 0; m < 4; m++) accC[i][m] += a[i] * p[m];
    }

    // --- stage 3: s_n = relu(h2) . W_eff, reduce over ty ---
    float part[4] = {0.f, 0.f, 0.f, 0.f};
    #pragma unroll
    for (int i = 0; i < 4; i++)
        #pragma unroll
        for (int m = 0; m < 4; m++) {
            int j = 4 * ty + m;
            float h2 = fmaxf(accC[i][m] + sb3[j], 0.f);
            part[i] += h2 * swe[j];
        }
    #pragma unroll
    for (int i = 0; i < 4; i++)
        atomicAdd(&snode[4 * tx + i], part[i]);
    __syncthreads();

    if (tid < 64) {
        int node = node0 + tid;
        if (node < N_NODES) {
            atomicAdd(&out[gid[node]], snode[tid] + g_c);
        }
    }
}

// ---------------------------------------------------------------------------
// kernel_launch
// inputs: 0 node_feats, 1 edge_feats(unused), 2 src, 3 dst, 4 graph_ids,
//         5 W_gcn, 6 b_gcn, 7 W_res, 8 b_res, 9 W_in, 10 b_in,
//         11 W_out, 12 b_out, 13 W_pred, 14 b_pred
// ---------------------------------------------------------------------------
extern "C" void kernel_launch(void* const* d_in, const int* in_sizes, int n_in,
                              void* d_out, int out_size) {
    const float* nf     = (const float*)d_in[0];
    const int*   src    = (const int*)d_in[2];
    const int*   dst    = (const int*)d_in[3];
    const int*   gids   = (const int*)d_in[4];
    const float* W_gcn  = (const float*)d_in[5];
    const float* b_gcn  = (const float*)d_in[6];
    const float* W_res  = (const float*)d_in[7];
    const float* b_res  = (const float*)d_in[8];
    const float* W_in   = (const float*)d_in[9];
    const float* b_in   = (const float*)d_in[10];
    const float* W_out  = (const float*)d_in[11];
    const float* b_out  = (const float*)d_in[12];
    const float* W_pred = (const float*)d_in[13];
    const float* b_pred = (const float*)d_in[14];
    float* out = (float*)d_out;

    cudaFuncSetAttribute(k_nodes, cudaFuncAttributeMaxDynamicSharedMemorySize,
                         SMEM_BYTES);

    k_zero_agg<<<(N_NODES * D / 4 + 255) / 256, 256>>>();
    k_prep<<<1, 256>>>(W_out, b_out, W_pred, b_pred, out);
    {
        long long total = (long long)N_EDGES * 16;
        int grid = (int)((total + 255) / 256);
        k_edges<<<grid, 256>>>(nf, src, dst);
    }
    {
        int grid = (N_NODES + 63) / 64;
        k_nodes<<<grid, 256, SMEM_BYTES>>>(nf, gids,
                                           W_gcn, b_gcn, W_res, b_res,
                                           W_in, b_in, out);
    }
}

// round 2
// speedup vs baseline: 1.5794x; 1.5794x over previous
#include <cuda_runtime.h>

#define N_NODES   100000
#define N_EDGES   1200000
#define D         64
#define G_FEAT    128
#define N_GRAPHS  256

// Scratch (no allocations allowed -> __device__ globals)
__device__ __align__(16) float g_agg[N_NODES * D];   // 25.6 MB
__device__ float g_Weff[D];
__device__ float g_c;

// ---------------------------------------------------------------------------
// Zero the aggregation buffer (float4 stores)
// ---------------------------------------------------------------------------
__global__ void k_zero_agg() {
    int i = blockIdx.x * blockDim.x + threadIdx.x;
    if (i < (N_NODES * D) / 4) {
        ((float4*)g_agg)[i] = make_float4(0.f, 0.f, 0.f, 0.f);
    }
}

// ---------------------------------------------------------------------------
// Precompute W_eff = W_out @ W_pred, c = b_out . W_pred, init out = b_pred
// ---------------------------------------------------------------------------
__global__ void k_prep(const float* __restrict__ W_out,
                       const float* __restrict__ b_out,
                       const float* __restrict__ W_pred,
                       const float* __restrict__ b_pred,
                       float* __restrict__ out) {
    int t = threadIdx.x;
    if (t < D) {
        float s = 0.f;
        #pragma unroll 4
        for (int f = 0; f < G_FEAT; f++) s += W_out[t * G_FEAT + f] * W_pred[f];
        g_Weff[t] = s;
    }
    if (t == 0) {
        float s = 0.f;
        for (int f = 0; f < G_FEAT; f++) s += b_out[f] * W_pred[f];
        g_c = s;
    }
    if (t < N_GRAPHS) out[t] = b_pred[0];
}

// ---------------------------------------------------------------------------
// Edge scatter: agg[dst] += node_feats[src].
// 16 threads per edge, one red.global.add.v4.f32 (16B vector reduction) each.
// ---------------------------------------------------------------------------
__global__ void __launch_bounds__(256) k_edges(const float* __restrict__ nf,
                                               const int* __restrict__ src,
                                               const int* __restrict__ dst) {
    long long t = (long long)blockIdx.x * blockDim.x + threadIdx.x;
    int e = (int)(t >> 4);
    int j = (int)(t & 15);
    if (e >= N_EDGES) return;
    int s = src[e];
    int d = dst[e];
    float4 v = ((const float4*)(nf + (size_t)s * D))[j];
    float* p = g_agg + (size_t)d * D + j * 4;
    asm volatile("red.global.add.v4.f32 [%0], {%1, %2, %3, %4};"
                 :: "l"(p), "f"(v.x), "f"(v.y), "f"(v.z), "f"(v.w)
                 : "memory");
}

// ---------------------------------------------------------------------------
// Fused node pipeline, v2: 128 threads/CTA, 128 nodes/CTA, 8x8 thread tiles.
//   h  = relu(agg@W1+b1) + relu(x@W2+b2)
//   h2 = relu(h@W3+b3)
//   s  = h2 . W_eff ;  out[gid[n]] += s + c
// Stages sequential; one 16KB weight buffer reloaded per stage.
// ---------------------------------------------------------------------------
#define NT   128
#define NPC  128
#define SN   128
// smem floats: W 4096 + sT 8192 + sH 8192 + 4*64 biases + 128 snode
#define SMEM_FLOATS (4096 + 8192 + 8192 + 256 + 128)
#define SMEM_BYTES  (SMEM_FLOATS * 4)

__global__ void __launch_bounds__(NT, 2) k_nodes(
    const float* __restrict__ nf, const int* __restrict__ gid,
    const float* __restrict__ W1, const float* __restrict__ b1,
    const float* __restrict__ W2, const float* __restrict__ b2,
    const float* __restrict__ W3, const float* __restrict__ b3,
    float* __restrict__ out) {

    extern __shared__ __align__(16) float sm[];
    float* sW    = sm;                 // [64][64]  current weight, k-major
    float* sT    = sW + 4096;          // [64][SN]  input tile, k-major
    float* sH    = sT + 64 * SN;       // [64][SN]  h tile, feat-major
    float* sb1   = sH + 64 * SN;
    float* sb2   = sb1 + 64;
    float* sb3   = sb2 + 64;
    float* swe   = sb3 + 64;
    float* snode = swe + 64;           // [128]

    int tid = threadIdx.x;
    int node0 = blockIdx.x * NPC;
    int node  = node0 + tid;
    bool ok   = node < N_NODES;

    if (tid < 64) {
        sb1[tid] = b1[tid];
        sb2[tid] = b2[tid];
        sb3[tid] = b3[tid];
        swe[tid] = g_Weff[tid];
    }
    snode[tid] = 0.f;

    // --- load aggT into sT (thread = one node row, transposed scalar stores) ---
    {
        const float4* rowp = (const float4*)(g_agg + (size_t)node * D);
        #pragma unroll
        for (int q = 0; q < 16; q++) {
            float4 v = ok ? rowp[q] : make_float4(0.f, 0.f, 0.f, 0.f);
            int k = q * 4;
            sT[(k + 0) * SN + tid] = v.x;
            sT[(k + 1) * SN + tid] = v.y;
            sT[(k + 2) * SN + tid] = v.z;
            sT[(k + 3) * SN + tid] = v.w;
        }
    }
    // --- load W1 ---
    #pragma unroll
    for (int i = 0; i < 8; i++)
        ((float4*)sW)[tid + i * NT] = ((const float4*)W1)[tid + i * NT];
    __syncthreads();

    int ng = tid & 15;     // node group -> nodes 8*ng..8*ng+7
    int fg = tid >> 4;     // feat group -> feats 8*fg..8*fg+7
    int nb = 8 * ng, fb = 8 * fg;

    // ===== stage 1: rH = relu(agg @ W1 + b1), kept in registers =====
    float acc[8][8];
    #pragma unroll
    for (int i = 0; i < 8; i++)
        #pragma unroll
        for (int m = 0; m < 8; m++) acc[i][m] = 0.f;

    #pragma unroll 4
    for (int k = 0; k < 64; k++) {
        float4 a0 = *(const float4*)(sT + k * SN + nb);
        float4 a1 = *(const float4*)(sT + k * SN + nb + 4);
        float4 w0 = *(const float4*)(sW + k * 64 + fb);
        float4 w1 = *(const float4*)(sW + k * 64 + fb + 4);
        float a[8] = {a0.x, a0.y, a0.z, a0.w, a1.x, a1.y, a1.z, a1.w};
        float w[8] = {w0.x, w0.y, w0.z, w0.w, w1.x, w1.y, w1.z, w1.w};
        #pragma unroll
        for (int i = 0; i < 8; i++)
            #pragma unroll
            for (int m = 0; m < 8; m++) acc[i][m] += a[i] * w[m];
    }

    float rH[8][8];
    #pragma unroll
    for (int i = 0; i < 8; i++)
        #pragma unroll
        for (int m = 0; m < 8; m++)
            rH[i][m] = fmaxf(acc[i][m] + sb1[fb + m], 0.f);

    __syncthreads();   // everyone done reading sT / sW

    // --- load xT into sT, W2 into sW ---
    {
        const float4* rowp = (const float4*)(nf + (size_t)node * D);
        #pragma unroll
        for (int q = 0; q < 16; q++) {
            float4 v = ok ? rowp[q] : make_float4(0.f, 0.f, 0.f, 0.f);
            int k = q * 4;
            sT[(k + 0) * SN + tid] = v.x;
            sT[(k + 1) * SN + tid] = v.y;
            sT[(k + 2) * SN + tid] = v.z;
            sT[(k + 3) * SN + tid] = v.w;
        }
    }
    #pragma unroll
    for (int i = 0; i < 8; i++)
        ((float4*)sW)[tid + i * NT] = ((const float4*)W2)[tid + i * NT];
    __syncthreads();

    // ===== stage 2: h = rH + relu(x @ W2 + b2), write to sH (feat-major) =====
    #pragma unroll
    for (int i = 0; i < 8; i++)
        #pragma unroll
        for (int m = 0; m < 8; m++) acc[i][m] = 0.f;

    #pragma unroll 4
    for (int k = 0; k < 64; k++) {
        float4 a0 = *(const float4*)(sT + k * SN + nb);
        float4 a1 = *(const float4*)(sT + k * SN + nb + 4);
        float4 w0 = *(const float4*)(sW + k * 64 + fb);
        float4 w1 = *(const float4*)(sW + k * 64 + fb + 4);
        float a[8] = {a0.x, a0.y, a0.z, a0.w, a1.x, a1.y, a1.z, a1.w};
        float w[8] = {w0.x, w0.y, w0.z, w0.w, w1.x, w1.y, w1.z, w1.w};
        #pragma unroll
        for (int i = 0; i < 8; i++)
            #pragma unroll
            for (int m = 0; m < 8; m++) acc[i][m] += a[i] * w[m];
    }

    #pragma unroll
    for (int m = 0; m < 8; m++) {
        float h0 = rH[0][m] + fmaxf(acc[0][m] + sb2[fb + m], 0.f);
        float h1 = rH[1][m] + fmaxf(acc[1][m] + sb2[fb + m], 0.f);
        float h2 = rH[2][m] + fmaxf(acc[2][m] + sb2[fb + m], 0.f);
        float h3 = rH[3][m] + fmaxf(acc[3][m] + sb2[fb + m], 0.f);
        float h4 = rH[4][m] + fmaxf(acc[4][m] + sb2[fb + m], 0.f);
        float h5 = rH[5][m] + fmaxf(acc[5][m] + sb2[fb + m], 0.f);
        float h6 = rH[6][m] + fmaxf(acc[6][m] + sb2[fb + m], 0.f);
        float h7 = rH[7][m] + fmaxf(acc[7][m] + sb2[fb + m], 0.f);
        *(float4*)(sH + (fb + m) * SN + nb)     = make_float4(h0, h1, h2, h3);
        *(float4*)(sH + (fb + m) * SN + nb + 4) = make_float4(h4, h5, h6, h7);
    }
    __syncthreads();   // sH complete; sW free

    // --- load W3 ---
    #pragma unroll
    for (int i = 0; i < 8; i++)
        ((float4*)sW)[tid + i * NT] = ((const float4*)W3)[tid + i * NT];
    __syncthreads();

    // ===== stage 3: h2 = relu(h @ W3 + b3); s_n = h2 . W_eff =====
    #pragma unroll
    for (int i = 0; i < 8; i++)
        #pragma unroll
        for (int m = 0; m < 8; m++) acc[i][m] = 0.f;

    #pragma unroll 4
    for (int k = 0; k < 64; k++) {
        float4 a0 = *(const float4*)(sH + k * SN + nb);
        float4 a1 = *(const float4*)(sH + k * SN + nb + 4);
        float4 w0 = *(const float4*)(sW + k * 64 + fb);
        float4 w1 = *(const float4*)(sW + k * 64 + fb + 4);
        float a[8] = {a0.x, a0.y, a0.z, a0.w, a1.x, a1.y, a1.z, a1.w};
        float w[8] = {w0.x, w0.y, w0.z, w0.w, w1.x, w1.y, w1.z, w1.w};
        #pragma unroll
        for (int i = 0; i < 8; i++)
            #pragma unroll
            for (int m = 0; m < 8; m++) acc[i][m] += a[i] * w[m];
    }

    float part[8];
    #pragma unroll
    for (int i = 0; i < 8; i++) part[i] = 0.f;
    #pragma unroll
    for (int m = 0; m < 8; m++) {
        int j = fb + m;
        float bj = sb3[j], wj = swe[j];
        #pragma unroll
        for (int i = 0; i < 8; i++)
            part[i] += fmaxf(acc[i][m] + bj, 0.f) * wj;
    }
    #pragma unroll
    for (int i = 0; i < 8; i++)
        atomicAdd(&snode[nb + i], part[i]);
    __syncthreads();

    if (ok) atomicAdd(&out[gid[node]], snode[tid] + g_c);
}

// ---------------------------------------------------------------------------
// kernel_launch
// inputs: 0 node_feats, 1 edge_feats(unused), 2 src, 3 dst, 4 graph_ids,
//         5 W_gcn, 6 b_gcn, 7 W_res, 8 b_res, 9 W_in, 10 b_in,
//         11 W_out, 12 b_out, 13 W_pred, 14 b_pred
// ---------------------------------------------------------------------------
extern "C" void kernel_launch(void* const* d_in, const int* in_sizes, int n_in,
                              void* d_out, int out_size) {
    const float* nf     = (const float*)d_in[0];
    const int*   src    = (const int*)d_in[2];
    const int*   dst    = (const int*)d_in[3];
    const int*   gids   = (const int*)d_in[4];
    const float* W_gcn  = (const float*)d_in[5];
    const float* b_gcn  = (const float*)d_in[6];
    const float* W_res  = (const float*)d_in[7];
    const float* b_res  = (const float*)d_in[8];
    const float* W_in   = (const float*)d_in[9];
    const float* b_in   = (const float*)d_in[10];
    const float* W_out  = (const float*)d_in[11];
    const float* b_out  = (const float*)d_in[12];
    const float* W_pred = (const float*)d_in[13];
    const float* b_pred = (const float*)d_in[14];
    float* out = (float*)d_out;

    cudaFuncSetAttribute(k_nodes, cudaFuncAttributeMaxDynamicSharedMemorySize,
                         SMEM_BYTES);

    k_zero_agg<<<(N_NODES * D / 4 + 255) / 256, 256>>>();
    k_prep<<<1, 256>>>(W_out, b_out, W_pred, b_pred, out);
    {
        long long total = (long long)N_EDGES * 16;
        int grid = (int)((total + 255) / 256);
        k_edges<<<grid, 256>>>(nf, src, dst);
    }
    {
        int grid = (N_NODES + NPC - 1) / NPC;
        k_nodes<<<grid, NT, SMEM_BYTES>>>(nf, gids,
                                          W_gcn, b_gcn, W_res, b_res,
                                          W_in, b_in, out);
    }
}

// round 7
// speedup vs baseline: 1.8485x; 1.1704x over previous
#include <cuda_runtime.h>
#include <cstdint>

#define N_NODES   100000
#define N_EDGES   1200000
#define D         64
#define G_FEAT    128
#define N_GRAPHS  256

// Scratch (no allocations allowed -> __device__ globals)
__device__ __align__(16) float g_agg[N_NODES * D];   // 25.6 MB
__device__ float g_Weff[D];
__device__ float g_c;

// ---------------------------------------------------------------------------
// helpers
// ---------------------------------------------------------------------------
__device__ __forceinline__ unsigned f2tf(float f) {
    unsigned u;
    asm("cvt.rna.tf32.f32 %0, %1;" : "=r"(u) : "f"(f));
    return u;
}

__device__ __forceinline__ void mma_tf32(float* d, const unsigned* a,
                                         const unsigned* b) {
    asm volatile(
        "mma.sync.aligned.m16n8k8.row.col.f32.tf32.tf32.f32 "
        "{%0,%1,%2,%3}, {%4,%5,%6,%7}, {%8,%9}, {%0,%1,%2,%3};"
        : "+f"(d[0]), "+f"(d[1]), "+f"(d[2]), "+f"(d[3])
        : "r"(a[0]), "r"(a[1]), "r"(a[2]), "r"(a[3]),
          "r"(b[0]), "r"(b[1]));
}

// ---------------------------------------------------------------------------
// Zero the aggregation buffer
// ---------------------------------------------------------------------------
__global__ void k_zero_agg() {
    int i = blockIdx.x * blockDim.x + threadIdx.x;
    if (i < (N_NODES * D) / 4) {
        ((float4*)g_agg)[i] = make_float4(0.f, 0.f, 0.f, 0.f);
    }
}

// ---------------------------------------------------------------------------
// Precompute W_eff = W_out @ W_pred, c = b_out . W_pred, init out = b_pred
// ---------------------------------------------------------------------------
__global__ void k_prep(const float* __restrict__ W_out,
                       const float* __restrict__ b_out,
                       const float* __restrict__ W_pred,
                       const float* __restrict__ b_pred,
                       float* __restrict__ out) {
    int t = threadIdx.x;
    if (t < D) {
        float s = 0.f;
        #pragma unroll 4
        for (int f = 0; f < G_FEAT; f++) s += W_out[t * G_FEAT + f] * W_pred[f];
        g_Weff[t] = s;
    }
    if (t == 0) {
        float s = 0.f;
        for (int f = 0; f < G_FEAT; f++) s += b_out[f] * W_pred[f];
        g_c = s;
    }
    if (t < N_GRAPHS) out[t] = b_pred[0];
}

// ---------------------------------------------------------------------------
// Edge scatter: agg[dst] += node_feats[src]. 16 threads/edge, one
// red.global.add.v4.f32 each (LTS-atomic-op bound, ~60us).
// ---------------------------------------------------------------------------
__global__ void __launch_bounds__(256) k_edges(const float* __restrict__ nf,
                                               const int* __restrict__ src,
                                               const int* __restrict__ dst) {
    long long t = (long long)blockIdx.x * blockDim.x + threadIdx.x;
    int e = (int)(t >> 4);
    int j = (int)(t & 15);
    if (e >= N_EDGES) return;
    int s = src[e];
    int d = dst[e];
    float4 v = ((const float4*)(nf + (size_t)s * D))[j];
    float* p = g_agg + (size_t)d * D + j * 4;
    asm volatile("red.global.add.v4.f32 [%0], {%1, %2, %3, %4};"
                 :: "l"(p), "f"(v.x), "f"(v.y), "f"(v.z), "f"(v.w)
                 : "memory");
}

// ---------------------------------------------------------------------------
// Fused node pipeline, v3: tf32 mma.sync tensor-core GEMMs.
//   h  = relu(agg@W1+b1) + relu(x@W2+b2)
//   h2 = relu(h@W3+b3)
//   s  = h2 . W_eff ;  out[gid[n]] += s + c
// CTA: 128 threads (4 warps), 128 nodes. Warp = 32 nodes (2 m16 tiles) x N=64.
// Operands pre-rounded to tf32 in smem; stride 68 -> conflict-free frags.
// ---------------------------------------------------------------------------
#define NT    128
#define NPC   128
#define SROW  68
#define SMEM_U32 (NPC * SROW + 3 * 64 * SROW + 256)
#define SMEM_BYTES (SMEM_U32 * 4)

// one K8-step of B fragments (8 n-tiles), A fragments (2 m-tiles), 16 mma
#define GEMM64(sWsel)                                                        \
    {                                                                        \
        _Pragma("unroll")                                                    \
        for (int k0 = 0; k0 < 8; k0++) {                                     \
            unsigned bfr[8][2];                                              \
            _Pragma("unroll")                                                \
            for (int t = 0; t < 8; t++) {                                    \
                const unsigned* p = (sWsel) + (8*t + g) * SROW + k0*8 + c;   \
                bfr[t][0] = p[0];                                            \
                bfr[t][1] = p[4];                                            \
            }                                                                \
            _Pragma("unroll")                                                \
            for (int mt = 0; mt < 2; mt++) {                                 \
                const unsigned* ap =                                         \
                    sA + (warp*32 + mt*16 + g) * SROW + k0*8 + c;            \
                unsigned afr[4];                                             \
                afr[0] = ap[0];                                              \
                afr[1] = ap[8*SROW];                                         \
                afr[2] = ap[4];                                              \
                afr[3] = ap[8*SROW + 4];                                     \
                _Pragma("unroll")                                            \
                for (int t = 0; t < 8; t++) mma_tf32(acc[mt][t], afr, bfr[t]);\
            }                                                                \
        }                                                                    \
    }

#define ZERO_ACC()                                                           \
    _Pragma("unroll")                                                        \
    for (int mt = 0; mt < 2; mt++)                                           \
        _Pragma("unroll")                                                    \
        for (int t = 0; t < 8; t++)                                          \
            _Pragma("unroll")                                                \
            for (int i = 0; i < 4; i++) acc[mt][t][i] = 0.f;

__global__ void __launch_bounds__(NT, 2) k_nodes(
    const float* __restrict__ nf, const int* __restrict__ gid,
    const float* __restrict__ W1, const float* __restrict__ b1,
    const float* __restrict__ W2, const float* __restrict__ b2,
    const float* __restrict__ W3, const float* __restrict__ b3,
    float* __restrict__ out) {

    extern __shared__ __align__(16) unsigned smu[];
    unsigned* sA = smu;                    // [128][SROW] tf32 input tile
    unsigned* sW = sA + NPC * SROW;        // [3][64][SROW]  Wt[n][k] tf32
    float*    sb = (float*)(sW + 3 * 64 * SROW); // b1|b2|b3|we (4*64)

    int tid  = threadIdx.x;
    int lane = tid & 31;
    int warp = tid >> 5;
    int g    = lane >> 2;      // groupID (row within m16)
    int c    = lane & 3;       // thread-in-group (col quad)

    if (tid < 64) {
        sb[tid]       = b1[tid];
        sb[64 + tid]  = b2[tid];
        sb[128 + tid] = b3[tid];
        sb[192 + tid] = g_Weff[tid];
    }

    // --- load + transpose weights: sW[m][n][k] = tf32(Wm[k][n]) ---
    {
        int n  = tid >> 1;
        int kh = (tid & 1) * 32;
        const float* Ws[3] = {W1, W2, W3};
        #pragma unroll
        for (int m = 0; m < 3; m++) {
            unsigned* drow = sW + m * 64 * SROW + n * SROW;
            const float* scol = Ws[m] + n;
            #pragma unroll 8
            for (int kk = 0; kk < 32; kk++)
                drow[kh + kk] = f2tf(scol[(kh + kk) * 64]);
        }
    }

    int node0 = blockIdx.x * NPC;
    int node  = node0 + tid;
    bool ok   = node < N_NODES;
    float cterm = g_c;

    // --- stage R input: x tile (row-major, tf32) ---
    {
        const float4* rp = (const float4*)(nf + (size_t)node * D);
        unsigned* drow = sA + tid * SROW;
        #pragma unroll
        for (int q = 0; q < 16; q++) {
            float4 v = ok ? rp[q] : make_float4(0.f, 0.f, 0.f, 0.f);
            *(uint4*)(drow + 4*q) =
                make_uint4(f2tf(v.x), f2tf(v.y), f2tf(v.z), f2tf(v.w));
        }
    }
    __syncthreads();

    float acc[2][8][4];

    // ===== residual: r2 = relu(x @ W2 + b2), kept in registers =====
    ZERO_ACC();
    GEMM64(sW + 1 * 64 * SROW);

    float r2[2][8][4];
    #pragma unroll
    for (int mt = 0; mt < 2; mt++)
        #pragma unroll
        for (int t = 0; t < 8; t++) {
            int c0 = 8*t + 2*c, c1 = c0 + 1;
            r2[mt][t][0] = fmaxf(acc[mt][t][0] + sb[64 + c0], 0.f);
            r2[mt][t][1] = fmaxf(acc[mt][t][1] + sb[64 + c1], 0.f);
            r2[mt][t][2] = fmaxf(acc[mt][t][2] + sb[64 + c0], 0.f);
            r2[mt][t][3] = fmaxf(acc[mt][t][3] + sb[64 + c1], 0.f);
        }
    __syncthreads();

    // --- stage 1 input: agg tile ---
    {
        const float4* rp = (const float4*)(g_agg + (size_t)node * D);
        unsigned* drow = sA + tid * SROW;
        #pragma unroll
        for (int q = 0; q < 16; q++) {
            float4 v = ok ? rp[q] : make_float4(0.f, 0.f, 0.f, 0.f);
            *(uint4*)(drow + 4*q) =
                make_uint4(f2tf(v.x), f2tf(v.y), f2tf(v.z), f2tf(v.w));
        }
    }
    __syncthreads();

    // ===== stage 1: h = relu(agg @ W1 + b1) + r2 =====
    ZERO_ACC();
    GEMM64(sW);

    float h[2][8][4];
    #pragma unroll
    for (int mt = 0; mt < 2; mt++)
        #pragma unroll
        for (int t = 0; t < 8; t++) {
            int c0 = 8*t + 2*c, c1 = c0 + 1;
            h[mt][t][0] = fmaxf(acc[mt][t][0] + sb[c0], 0.f) + r2[mt][t][0];
            h[mt][t][1] = fmaxf(acc[mt][t][1] + sb[c1], 0.f) + r2[mt][t][1];
            h[mt][t][2] = fmaxf(acc[mt][t][2] + sb[c0], 0.f) + r2[mt][t][2];
            h[mt][t][3] = fmaxf(acc[mt][t][3] + sb[c1], 0.f) + r2[mt][t][3];
        }
    __syncthreads();

    // --- write h (C-layout) back into sA as tf32 A-tile ---
    #pragma unroll
    for (int mt = 0; mt < 2; mt++)
        #pragma unroll
        for (int t = 0; t < 8; t++) {
            int r0 = warp*32 + mt*16 + g;
            int col = 8*t + 2*c;
            *(uint2*)(sA + r0 * SROW + col) =
                make_uint2(f2tf(h[mt][t][0]), f2tf(h[mt][t][1]));
            *(uint2*)(sA + (r0 + 8) * SROW + col) =
                make_uint2(f2tf(h[mt][t][2]), f2tf(h[mt][t][3]));
        }
    __syncthreads();

    // ===== stage 2: h2 = relu(h @ W3 + b3);  s = h2 . W_eff =====
    ZERO_ACC();
    GEMM64(sW + 2 * 64 * SROW);

    #pragma unroll
    for (int mt = 0; mt < 2; mt++) {
        float s0 = 0.f, s1 = 0.f;     // rows g, g+8 of this m-tile
        #pragma unroll
        for (int t = 0; t < 8; t++) {
            int c0 = 8*t + 2*c, c1 = c0 + 1;
            float b0 = sb[128 + c0], b1v = sb[128 + c1];
            float w0 = sb[192 + c0], w1v = sb[192 + c1];
            s0 += fmaxf(acc[mt][t][0] + b0, 0.f) * w0
                + fmaxf(acc[mt][t][1] + b1v, 0.f) * w1v;
            s1 += fmaxf(acc[mt][t][2] + b0, 0.f) * w0
                + fmaxf(acc[mt][t][3] + b1v, 0.f) * w1v;
        }
        // reduce over the 4 lanes of the c-group
        s0 += __shfl_xor_sync(0xffffffffu, s0, 1);
        s0 += __shfl_xor_sync(0xffffffffu, s0, 2);
        s1 += __shfl_xor_sync(0xffffffffu, s1, 1);
        s1 += __shfl_xor_sync(0xffffffffu, s1, 2);
        if (c == 0) {
            int n0 = node0 + warp*32 + mt*16 + g;
            if (n0 < N_NODES)     atomicAdd(&out[gid[n0]],     s0 + cterm);
            if (n0 + 8 < N_NODES) atomicAdd(&out[gid[n0 + 8]], s1 + cterm);
        }
    }
}

// ---------------------------------------------------------------------------
// kernel_launch
// inputs: 0 node_feats, 1 edge_feats(unused), 2 src, 3 dst, 4 graph_ids,
//         5 W_gcn, 6 b_gcn, 7 W_res, 8 b_res, 9 W_in, 10 b_in,
//         11 W_out, 12 b_out, 13 W_pred, 14 b_pred
// ---------------------------------------------------------------------------
extern "C" void kernel_launch(void* const* d_in, const int* in_sizes, int n_in,
                              void* d_out, int out_size) {
    const float* nf     = (const float*)d_in[0];
    const int*   src    = (const int*)d_in[2];
    const int*   dst    = (const int*)d_in[3];
    const int*   gids   = (const int*)d_in[4];
    const float* W_gcn  = (const float*)d_in[5];
    const float* b_gcn  = (const float*)d_in[6];
    const float* W_res  = (const float*)d_in[7];
    const float* b_res  = (const float*)d_in[8];
    const float* W_in   = (const float*)d_in[9];
    const float* b_in   = (const float*)d_in[10];
    const float* W_out  = (const float*)d_in[11];
    const float* b_out  = (const float*)d_in[12];
    const float* W_pred = (const float*)d_in[13];
    const float* b_pred = (const float*)d_in[14];
    float* out = (float*)d_out;

    cudaFuncSetAttribute(k_nodes, cudaFuncAttributeMaxDynamicSharedMemorySize,
                         SMEM_BYTES);

    k_zero_agg<<<(N_NODES * D / 4 + 255) / 256, 256>>>();
    k_prep<<<1, 256>>>(W_out, b_out, W_pred, b_pred, out);
    {
        long long total = (long long)N_EDGES * 16;
        int grid = (int)((total + 255) / 256);
        k_edges<<<grid, 256>>>(nf, src, dst);
    }
    {
        int grid = (N_NODES + NPC - 1) / NPC;
        k_nodes<<<grid, NT, SMEM_BYTES>>>(nf, gids,
                                          W_gcn, b_gcn, W_res, b_res,
                                          W_in, b_in, out);
    }
}

// round 8
// speedup vs baseline: 1.8891x; 1.0220x over previous
#include <cuda_runtime.h>
#include <cstdint>

#define N_NODES   100000
#define N_EDGES   1200000
#define D         64
#define G_FEAT    128
#define N_GRAPHS  256

// Scratch (no allocations allowed -> __device__ globals)
__device__ __align__(16) float g_agg[N_NODES * D];   // 25.6 MB
__device__ float g_Weff[D];
__device__ float g_c;
// Pre-built tf32 B-fragment table: [stage][ntile][kstep][lane] as uint2
// frag.x = tf32(W[(k0*8+c)*64 + n]), frag.y = tf32(W[(k0*8+c+4)*64 + n])
__device__ __align__(16) uint2 g_Bfrag[3 * 8 * 8 * 32];

// ---------------------------------------------------------------------------
// helpers
// ---------------------------------------------------------------------------
__device__ __forceinline__ unsigned f2tf(float f) {
    unsigned u;
    asm("cvt.rna.tf32.f32 %0, %1;" : "=r"(u) : "f"(f));
    return u;
}

__device__ __forceinline__ void mma_tf32(float* d, const unsigned* a,
                                         const unsigned* b) {
    asm volatile(
        "mma.sync.aligned.m16n8k8.row.col.f32.tf32.tf32.f32 "
        "{%0,%1,%2,%3}, {%4,%5,%6,%7}, {%8,%9}, {%0,%1,%2,%3};"
        : "+f"(d[0]), "+f"(d[1]), "+f"(d[2]), "+f"(d[3])
        : "r"(a[0]), "r"(a[1]), "r"(a[2]), "r"(a[3]),
          "r"(b[0]), "r"(b[1]));
}

// ---------------------------------------------------------------------------
// Zero the aggregation buffer
// ---------------------------------------------------------------------------
__global__ void k_zero_agg() {
    int i = blockIdx.x * blockDim.x + threadIdx.x;
    if (i < (N_NODES * D) / 4) {
        ((float4*)g_agg)[i] = make_float4(0.f, 0.f, 0.f, 0.f);
    }
}

// ---------------------------------------------------------------------------
// Precompute W_eff = W_out @ W_pred, c = b_out . W_pred, init out = b_pred
// ---------------------------------------------------------------------------
__global__ void k_prep(const float* __restrict__ W_out,
                       const float* __restrict__ b_out,
                       const float* __restrict__ W_pred,
                       const float* __restrict__ b_pred,
                       float* __restrict__ out) {
    int t = threadIdx.x;
    if (t < D) {
        float s = 0.f;
        #pragma unroll 4
        for (int f = 0; f < G_FEAT; f++) s += W_out[t * G_FEAT + f] * W_pred[f];
        g_Weff[t] = s;
    }
    if (t == 0) {
        float s = 0.f;
        for (int f = 0; f < G_FEAT; f++) s += b_out[f] * W_pred[f];
        g_c = s;
    }
    if (t < N_GRAPHS) out[t] = b_pred[0];
}

// ---------------------------------------------------------------------------
// Build the per-lane tf32 B-fragment table (one-time, ~2us).
// id = ((s*8 + t)*8 + k0)*32 + lane,  lane = g*4 + c,  n = 8t+g, k = k0*8+c
// ---------------------------------------------------------------------------
__global__ void k_wprep(const float* __restrict__ W1,
                        const float* __restrict__ W2,
                        const float* __restrict__ W3) {
    int id = blockIdx.x * blockDim.x + threadIdx.x;
    if (id >= 3 * 8 * 8 * 32) return;
    int lane = id & 31;
    int k0   = (id >> 5) & 7;
    int t    = (id >> 8) & 7;
    int s    = id >> 11;
    const float* W = (s == 0) ? W1 : ((s == 1) ? W2 : W3);
    int g = lane >> 2, c = lane & 3;
    int n = 8 * t + g;
    int k = k0 * 8 + c;
    uint2 v;
    v.x = f2tf(W[k * 64 + n]);
    v.y = f2tf(W[(k + 4) * 64 + n]);
    g_Bfrag[id] = v;
}

// ---------------------------------------------------------------------------
// Edge scatter: agg[dst] += node_feats[src]. 16 threads/edge, one
// red.global.add.v4.f32 each (LTS-atomic-op bound, ~60us).
// ---------------------------------------------------------------------------
__global__ void __launch_bounds__(256) k_edges(const float* __restrict__ nf,
                                               const int* __restrict__ src,
                                               const int* __restrict__ dst) {
    long long t = (long long)blockIdx.x * blockDim.x + threadIdx.x;
    int e = (int)(t >> 4);
    int j = (int)(t & 15);
    if (e >= N_EDGES) return;
    int s = src[e];
    int d = dst[e];
    float4 v = ((const float4*)(nf + (size_t)s * D))[j];
    float* p = g_agg + (size_t)d * D + j * 4;
    asm volatile("red.global.add.v4.f32 [%0], {%1, %2, %3, %4};"
                 :: "l"(p), "f"(v.x), "f"(v.y), "f"(v.z), "f"(v.w)
                 : "memory");
}

// ---------------------------------------------------------------------------
// Fused node pipeline, v4: tf32 mma, occupancy-oriented.
//   h  = relu(agg@W1+b1) + relu(x@W2+b2)
//   h2 = relu(h@W3+b3);  s = h2 . W_eff;  out[gid[n]] += s + c
// CTA: 256 threads (8 warps), 128 nodes. Warp = 16 nodes (1 m16 tile) x N=64.
// B-fragments from the prebuilt gmem table (L1-resident, warp-uniform).
// smem: two input tiles (x, agg); h is written back into the x tile.
// 3 syncthreads total; launch_bounds(256,2) -> 16 warps/SM.
// ---------------------------------------------------------------------------
#define NT    256
#define NPC   128
#define SROW  68
#define SMEM_U32 (2 * NPC * SROW + 256)
#define SMEM_BYTES (SMEM_U32 * 4)

// one 16x64x64 GEMM: A rows [warp*16 .. +15] from smem `tile`, B frags from sB
#define GEMM64T(tile, sB)                                                    \
    {                                                                        \
        _Pragma("unroll")                                                    \
        for (int k0 = 0; k0 < 8; k0++) {                                     \
            uint2 bfr[8];                                                    \
            _Pragma("unroll")                                                \
            for (int t = 0; t < 8; t++)                                      \
                bfr[t] = (sB)[(t * 8 + k0) * 32 + lane];                     \
            const unsigned* ap = (tile) + arow * SROW + k0 * 8 + c;          \
            unsigned afr[4];                                                 \
            afr[0] = ap[0];                                                  \
            afr[1] = ap[8 * SROW];                                           \
            afr[2] = ap[4];                                                  \
            afr[3] = ap[8 * SROW + 4];                                       \
            _Pragma("unroll")                                                \
            for (int t = 0; t < 8; t++)                                      \
                mma_tf32(acc[t], afr, (const unsigned*)&bfr[t]);             \
        }                                                                    \
    }

#define ZERO_ACC()                                                           \
    _Pragma("unroll")                                                        \
    for (int t = 0; t < 8; t++)                                              \
        _Pragma("unroll")                                                    \
        for (int i = 0; i < 4; i++) acc[t][i] = 0.f;

__global__ void __launch_bounds__(NT, 2) k_nodes(
    const float* __restrict__ nf, const int* __restrict__ gid,
    const float* __restrict__ b1, const float* __restrict__ b2,
    const float* __restrict__ b3, float* __restrict__ out) {

    extern __shared__ __align__(16) unsigned smu[];
    unsigned* sX = smu;                    // [128][SROW] x tile, later h tile
    unsigned* sG = sX + NPC * SROW;        // [128][SROW] agg tile
    float*    sb = (float*)(sG + NPC * SROW); // b1|b2|b3|we

    int tid  = threadIdx.x;
    int lane = tid & 31;
    int warp = tid >> 5;
    int g    = lane >> 2;
    int c    = lane & 3;
    int arow = warp * 16 + g;

    int node0 = blockIdx.x * NPC;

    if (tid < 64) {
        sb[tid]       = b1[tid];
        sb[64 + tid]  = b2[tid];
        sb[128 + tid] = b3[tid];
        sb[192 + tid] = g_Weff[tid];
    }

    // --- load x and agg tiles (thread = half a node row, 8 float4 each) ---
    {
        int r  = tid >> 1;
        int q0 = (tid & 1) * 8;
        bool ok = (node0 + r) < N_NODES;
        const float4* xp = (const float4*)(nf    + (size_t)(node0 + r) * D);
        const float4* gp = (const float4*)(g_agg + (size_t)(node0 + r) * D);
        unsigned* dX = sX + r * SROW;
        unsigned* dG = sG + r * SROW;
        #pragma unroll
        for (int u = 0; u < 8; u++) {
            int q = q0 + u;
            float4 v = ok ? xp[q] : make_float4(0.f, 0.f, 0.f, 0.f);
            *(uint4*)(dX + 4 * q) =
                make_uint4(f2tf(v.x), f2tf(v.y), f2tf(v.z), f2tf(v.w));
        }
        #pragma unroll
        for (int u = 0; u < 8; u++) {
            int q = q0 + u;
            float4 v = ok ? gp[q] : make_float4(0.f, 0.f, 0.f, 0.f);
            *(uint4*)(dG + 4 * q) =
                make_uint4(f2tf(v.x), f2tf(v.y), f2tf(v.z), f2tf(v.w));
        }
    }
    __syncthreads();

    const uint2* __restrict__ fr1 = g_Bfrag;           // W1 frags
    const uint2* __restrict__ fr2 = g_Bfrag + 2048;    // W2
    const uint2* __restrict__ fr3 = g_Bfrag + 4096;    // W3

    float acc[8][4];

    // ===== residual: r2 = relu(x @ W2 + b2) =====
    ZERO_ACC();
    GEMM64T(sX, fr2);

    float r2[8][4];
    #pragma unroll
    for (int t = 0; t < 8; t++) {
        int c0 = 8 * t + 2 * c, c1 = c0 + 1;
        r2[t][0] = fmaxf(acc[t][0] + sb[64 + c0], 0.f);
        r2[t][1] = fmaxf(acc[t][1] + sb[64 + c1], 0.f);
        r2[t][2] = fmaxf(acc[t][2] + sb[64 + c0], 0.f);
        r2[t][3] = fmaxf(acc[t][3] + sb[64 + c1], 0.f);
    }
    __syncthreads();   // all warps done reading sX (it becomes the h tile)

    // ===== stage 1: h = relu(agg @ W1 + b1) + r2, write h into sX =====
    ZERO_ACC();
    GEMM64T(sG, fr1);

    #pragma unroll
    for (int t = 0; t < 8; t++) {
        int c0 = 8 * t + 2 * c, c1 = c0 + 1;
        float h0 = fmaxf(acc[t][0] + sb[c0], 0.f) + r2[t][0];
        float h1 = fmaxf(acc[t][1] + sb[c1], 0.f) + r2[t][1];
        float h2 = fmaxf(acc[t][2] + sb[c0], 0.f) + r2[t][2];
        float h3 = fmaxf(acc[t][3] + sb[c1], 0.f) + r2[t][3];
        *(uint2*)(sX + arow * SROW + c0)       = make_uint2(f2tf(h0), f2tf(h1));
        *(uint2*)(sX + (arow + 8) * SROW + c0) = make_uint2(f2tf(h2), f2tf(h3));
    }
    __syncthreads();

    // ===== stage 2: h2 = relu(h @ W3 + b3);  s = h2 . W_eff =====
    ZERO_ACC();
    GEMM64T(sX, fr3);

    {
        float s0 = 0.f, s1 = 0.f;      // rows arow, arow+8
        #pragma unroll
        for (int t = 0; t < 8; t++) {
            int c0 = 8 * t + 2 * c, c1 = c0 + 1;
            float bb0 = sb[128 + c0], bb1 = sb[128 + c1];
            float w0  = sb[192 + c0], w1  = sb[192 + c1];
            s0 += fmaxf(acc[t][0] + bb0, 0.f) * w0
                + fmaxf(acc[t][1] + bb1, 0.f) * w1;
            s1 += fmaxf(acc[t][2] + bb0, 0.f) * w0
                + fmaxf(acc[t][3] + bb1, 0.f) * w1;
        }
        s0 += __shfl_xor_sync(0xffffffffu, s0, 1);
        s0 += __shfl_xor_sync(0xffffffffu, s0, 2);
        s1 += __shfl_xor_sync(0xffffffffu, s1, 1);
        s1 += __shfl_xor_sync(0xffffffffu, s1, 2);
        if (c == 0) {
            float cterm = g_c;
            int n0 = node0 + arow;
            if (n0 < N_NODES)     atomicAdd(&out[gid[n0]],     s0 + cterm);
            if (n0 + 8 < N_NODES) atomicAdd(&out[gid[n0 + 8]], s1 + cterm);
        }
    }
}

// ---------------------------------------------------------------------------
// kernel_launch
// inputs: 0 node_feats, 1 edge_feats(unused), 2 src, 3 dst, 4 graph_ids,
//         5 W_gcn, 6 b_gcn, 7 W_res, 8 b_res, 9 W_in, 10 b_in,
//         11 W_out, 12 b_out, 13 W_pred, 14 b_pred
// ---------------------------------------------------------------------------
extern "C" void kernel_launch(void* const* d_in, const int* in_sizes, int n_in,
                              void* d_out, int out_size) {
    const float* nf     = (const float*)d_in[0];
    const int*   src    = (const int*)d_in[2];
    const int*   dst    = (const int*)d_in[3];
    const int*   gids   = (const int*)d_in[4];
    const float* W_gcn  = (const float*)d_in[5];
    const float* b_gcn  = (const float*)d_in[6];
    const float* W_res  = (const float*)d_in[7];
    const float* b_res  = (const float*)d_in[8];
    const float* W_in   = (const float*)d_in[9];
    const float* b_in   = (const float*)d_in[10];
    const float* W_out  = (const float*)d_in[11];
    const float* b_out  = (const float*)d_in[12];
    const float* W_pred = (const float*)d_in[13];
    const float* b_pred = (const float*)d_in[14];
    float* out = (float*)d_out;

    cudaFuncSetAttribute(k_nodes, cudaFuncAttributeMaxDynamicSharedMemorySize,
                         SMEM_BYTES);

    k_zero_agg<<<(N_NODES * D / 4 + 255) / 256, 256>>>();
    k_prep<<<1, 256>>>(W_out, b_out, W_pred, b_pred, out);
    k_wprep<<<48, 128>>>(W_gcn, W_res, W_in);
    {
        long long total = (long long)N_EDGES * 16;
        int grid = (int)((total + 255) / 256);
        k_edges<<<grid, 256>>>(nf, src, dst);
    }
    {
        int grid = (N_NODES + NPC - 1) / NPC;
        k_nodes<<<grid, NT, SMEM_BYTES>>>(nf, gids, b_gcn, b_res, b_in, out);
    }
}